// round 16
// baseline (speedup 1.0000x reference)
#include <cuda_runtime.h>
#include <math.h>

// Problem constants
#define BATCH 8
#define NH    8
#define SEQQ  1024
#define SEQK  1024
#define DIM   512
#define HD    64
#define MROWS (BATCH*SEQQ)   // 8192

#define LN_EPS   1e-5f
#define MOFF     9.0f        // mask offset: exp(-9)=1.23e-4, normal in fp16

static __device__ float    g_q   [BATCH*SEQQ*DIM];
static __device__ unsigned g_qh  [BATCH*SEQQ*DIM/2];
static __device__ unsigned g_kh  [BATCH*SEQK*DIM/2];
static __device__ unsigned g_vh  [BATCH*SEQK*DIM/2];
static __device__ unsigned g_qin [BATCH*SEQQ*DIM/2];
static __device__ unsigned g_kin [BATCH*SEQK*DIM/2];
static __device__ unsigned g_wq  [DIM*DIM/2];
static __device__ unsigned g_wk  [DIM*DIM/2];
static __device__ unsigned g_wv  [DIM*DIM/2];
static __device__ unsigned g_wo  [DIM*DIM/2];   // g0-scaled Wo, half
static __device__ float    g_t0  [BATCH*SEQQ*DIM];
static __device__ unsigned g_t0h [BATCH*SEQQ*DIM/2];  // raw t0, half
static __device__ float    g_t1  [BATCH*SEQQ*DIM];
static __device__ float    g_part[MROWS*NH*2];  // per-(row,head) {sum, sumsq}
static __device__ float    g_gw  [DIM];         // G[n] = sum_k g0[k]*Wo[k,n]
static __device__ float    g_bw  [DIM];         // B[n] = sum_k b0[k]*Wo[k,n]

// ---------------------------------------------------------------------------
// helpers
// ---------------------------------------------------------------------------
__device__ __forceinline__ unsigned f2h2(float lo, float hi) {
    unsigned u;
    asm("{.reg .f16 l, h;\n\t"
        "cvt.rn.f16.f32 l, %1;\n\t"
        "cvt.rn.f16.f32 h, %2;\n\t"
        "mov.b32 %0, {l, h};}"
        : "=r"(u) : "f"(lo), "f"(hi));
    return u;
}

__device__ __forceinline__ void mma_f16(float* c, const unsigned* a, const unsigned* b) {
    asm volatile(
        "mma.sync.aligned.m16n8k16.row.col.f32.f16.f16.f32 "
        "{%0,%1,%2,%3},{%4,%5,%6,%7},{%8,%9},{%0,%1,%2,%3};"
        : "+f"(c[0]), "+f"(c[1]), "+f"(c[2]), "+f"(c[3])
        : "r"(a[0]), "r"(a[1]), "r"(a[2]), "r"(a[3]), "r"(b[0]), "r"(b[1]));
}

__device__ __forceinline__ void cp16(unsigned dst, const void* src) {
    asm volatile("cp.async.cg.shared.global [%0], [%1], 16;" :: "r"(dst), "l"(src));
}
__device__ __forceinline__ void cp_commit() {
    asm volatile("cp.async.commit_group;" ::: "memory");
}
template<int N>
__device__ __forceinline__ void cp_wait() {
    asm volatile("cp.async.wait_group %0;" :: "n"(N) : "memory");
}

__device__ __forceinline__ unsigned sm_addr(const void* p) {
    return (unsigned)__cvta_generic_to_shared(p);
}

__device__ __forceinline__ void ldsm_x4(unsigned& r0, unsigned& r1,
                                        unsigned& r2, unsigned& r3, unsigned a) {
    asm volatile("ldmatrix.sync.aligned.m8n8.x4.shared.b16 {%0,%1,%2,%3}, [%4];"
        : "=r"(r0), "=r"(r1), "=r"(r2), "=r"(r3) : "r"(a));
}
__device__ __forceinline__ void ldsm_x4t(unsigned& r0, unsigned& r1,
                                         unsigned& r2, unsigned& r3, unsigned a) {
    asm volatile("ldmatrix.sync.aligned.m8n8.x4.trans.shared.b16 {%0,%1,%2,%3}, [%4];"
        : "=r"(r0), "=r"(r1), "=r"(r2), "=r"(r3) : "r"(a));
}

// ---------------------------------------------------------------------------
// Combined conversion kernel; blockIdx.y selects job:
//   0,1: queries/keys f32->half   2,3,4: Wq/Wk/Wv f32->half
//   5: Wo scaled by g0[k] -> half 6: G[n],B[n] colsum reductions
// ---------------------------------------------------------------------------
__global__ __launch_bounds__(256)
void prep_k(const float* __restrict__ Xq, const float* __restrict__ Xk,
            const float* __restrict__ Wq, const float* __restrict__ Wk,
            const float* __restrict__ Wv, const float* __restrict__ Wo,
            const float* __restrict__ g0, const float* __restrict__ b0,
            unsigned* __restrict__ Yq, unsigned* __restrict__ Yk,
            unsigned* __restrict__ Ywq, unsigned* __restrict__ Ywk,
            unsigned* __restrict__ Ywv, unsigned* __restrict__ Ywo,
            float* __restrict__ Gw, float* __restrict__ Bw,
            int nBig, int nW)
{
    const int y = blockIdx.y;
    const int i = blockIdx.x * blockDim.x + threadIdx.x;

    if (y == 6) {   // colsum: G[n], B[n]
        if (blockIdx.x >= 2) return;
        const int n = blockIdx.x * 256 + threadIdx.x;
        float gsum = 0.f, bsum = 0.f;
        for (int k = 0; k < DIM; k++) {
            float w = Wo[(size_t)k * DIM + n];
            gsum = fmaf(g0[k], w, gsum);
            bsum = fmaf(b0[k], w, bsum);
        }
        Gw[n] = gsum; Bw[n] = bsum;
        return;
    }
    if (y == 5) {   // Wo row-scaled by g0
        if (i >= nW) return;
        const int k = i >> 7;               // DIM/4 = 128 groups per row
        const float g = g0[k];
        float4 t = ((const float4*)Wo)[i];
        ((uint2*)Ywo)[i] = make_uint2(f2h2(t.x * g, t.y * g),
                                      f2h2(t.z * g, t.w * g));
        return;
    }
    const float* X; unsigned* Y; int n4;
    switch (y) {
        case 0:  X = Xq; Y = Yq;  n4 = nBig; break;
        case 1:  X = Xk; Y = Yk;  n4 = nBig; break;
        case 2:  X = Wq; Y = Ywq; n4 = nW;   break;
        case 3:  X = Wk; Y = Ywk; n4 = nW;   break;
        default: X = Wv; Y = Ywv; n4 = nW;   break;
    }
    if (i < n4) {
        float4 t = ((const float4*)X)[i];
        ((uint2*)Y)[i] = make_uint2(f2h2(t.x, t.y), f2h2(t.z, t.w));
    }
}

// ---------------------------------------------------------------------------
// Dense NN GEMM (half inputs). BM=BN=128, BK=32, 4-stage cp.async.
// ---------------------------------------------------------------------------
#define HA_ST 40
#define HB_ST 136
#define GEMM_SMEM ((4*128*HA_ST + 4*32*HB_ST) * 2)

// Mainloop producing acc[2][8][4]; shared by qkv and wo kernels.
#define GEMM_MAINLOOP(A_, B_, m0_, n0_)                                         \
    unsigned short* As = hsm;                                                   \
    unsigned short* Bs = hsm + 4*128*HA_ST;                                     \
    const int K = DIM, N = DIM;                                                 \
    const int tid  = threadIdx.x;                                               \
    const int lane = tid & 31;                                                  \
    const int warp = tid >> 5;                                                  \
    const int g    = lane >> 2;                                                 \
    const int q    = lane & 3;                                                  \
    const int mBase = (warp & 3) * 32;                                          \
    const int nBase = (warp >> 2) * 64;                                         \
    const int amr[2] = { tid >> 2,        (tid + 256) >> 2 };                   \
    const int amc[2] = { (tid & 3) * 8,   ((tid + 256) & 3) * 8 };              \
    const int bkr[2] = { tid >> 4,        (tid + 256) >> 4 };                   \
    const int bnc[2] = { (tid & 15) * 8,  ((tid + 256) & 15) * 8 };             \
    const unsigned aB0 = sm_addr(As) +                                          \
        ((mBase + (lane & 15)) * HA_ST + (lane >> 4) * 8) * 2;                  \
    const unsigned bB0 = sm_addr(Bs) +                                          \
        (((lane & 7) + 8 * ((lane >> 3) & 1)) * HB_ST + nBase + (lane >> 4) * 8) * 2; \
    float acc[2][8][4];                                                         \
    _Pragma("unroll")                                                           \
    for (int i = 0; i < 2; i++)                                                 \
        _Pragma("unroll")                                                       \
        for (int j = 0; j < 8; j++)                                             \
            _Pragma("unroll")                                                   \
            for (int r = 0; r < 4; r++) acc[i][j][r] = 0.f;                     \
    const int NITER = K / 32;                                                   \
    _Pragma("unroll")                                                           \
    for (int s = 0; s < 3; s++) {                                               \
        const int k0 = s * 32;                                                  \
        _Pragma("unroll")                                                       \
        for (int r = 0; r < 2; r++) {                                           \
            cp16(sm_addr(As + (s*128 + amr[r])*HA_ST + amc[r]),                 \
                 A_ + (size_t)((m0_) + amr[r]) * K + k0 + amc[r]);              \
            cp16(sm_addr(Bs + (s*32 + bkr[r])*HB_ST + bnc[r]),                  \
                 B_ + (size_t)(k0 + bkr[r]) * N + (n0_) + bnc[r]);              \
        }                                                                       \
        cp_commit();                                                            \
    }                                                                           \
    for (int it = 0; it < NITER; it++) {                                        \
        cp_wait<2>();                                                           \
        __syncthreads();                                                        \
        if (it + 3 < NITER) {                                                   \
            const int s  = (it + 3) & 3;                                        \
            const int k0 = (it + 3) * 32;                                       \
            _Pragma("unroll")                                                   \
            for (int r = 0; r < 2; r++) {                                       \
                cp16(sm_addr(As + (s*128 + amr[r])*HA_ST + amc[r]),             \
                     A_ + (size_t)((m0_) + amr[r]) * K + k0 + amc[r]);          \
                cp16(sm_addr(Bs + (s*32 + bkr[r])*HB_ST + bnc[r]),              \
                     B_ + (size_t)(k0 + bkr[r]) * N + (n0_) + bnc[r]);          \
            }                                                                   \
        }                                                                       \
        cp_commit();                                                            \
        const unsigned aB = aB0 + (it & 3) * 128 * HA_ST * 2;                   \
        const unsigned bB = bB0 + (it & 3) * 32 * HB_ST * 2;                    \
        _Pragma("unroll")                                                       \
        for (int kc = 0; kc < 2; kc++) {                                        \
            unsigned a0[4], a1[4];                                              \
            ldsm_x4(a0[0], a0[1], a0[2], a0[3], aB + kc*32);                    \
            ldsm_x4(a1[0], a1[1], a1[2], a1[3], aB + 16*HA_ST*2 + kc*32);       \
            _Pragma("unroll")                                                   \
            for (int jp = 0; jp < 4; jp++) {                                    \
                unsigned b[4];                                                  \
                ldsm_x4t(b[0], b[1], b[2], b[3], bB + kc*16*HB_ST*2 + jp*32);   \
                mma_f16(acc[0][2*jp    ], a0, b    );                           \
                mma_f16(acc[0][2*jp + 1], a0, b + 2);                           \
                mma_f16(acc[1][2*jp    ], a1, b    );                           \
                mma_f16(acc[1][2*jp + 1], a1, b + 2);                           \
            }                                                                   \
        }                                                                       \
        __syncthreads();                                                        \
    }

// q/k/v projections in one launch: grid.x = 12; blockIdx.x>>2 selects.
__global__ __launch_bounds__(256, 2)
void gemm_qkv(const unsigned short* __restrict__ Aq, const unsigned short* __restrict__ Akv,
              const unsigned short* __restrict__ Bq, const unsigned short* __restrict__ Bk,
              const unsigned short* __restrict__ Bv,
              float* __restrict__ Cq, unsigned* __restrict__ Chq,
              unsigned* __restrict__ Chk, unsigned* __restrict__ Chv,
              const float* __restrict__ bq, const float* __restrict__ bk,
              const float* __restrict__ bv)
{
    extern __shared__ __align__(16) unsigned short hsm[];
    const int sel = blockIdx.x >> 2;
    const unsigned short* Ap = sel ? Akv : Aq;
    const unsigned short* Bp = (sel == 0) ? Bq : (sel == 1) ? Bk : Bv;
    unsigned* Ch             = (sel == 0) ? Chq : (sel == 1) ? Chk : Chv;
    const float* bias        = (sel == 0) ? bq : (sel == 1) ? bk : bv;
    float* C                 = (sel == 0) ? Cq : (float*)0;
    const int m0 = blockIdx.y * 128;
    const int n0 = (blockIdx.x & 3) * 128;

    GEMM_MAINLOOP(Ap, Bp, m0, n0)

    #pragma unroll
    for (int i = 0; i < 2; i++) {
        #pragma unroll
        for (int rr = 0; rr < 2; rr++) {
            int row = m0 + mBase + i * 16 + g + rr * 8;
            #pragma unroll
            for (int j = 0; j < 8; j++) {
                int col = n0 + nBase + j * 8 + 2 * q;
                float v0 = acc[i][j][rr*2 + 0] + bias[col];
                float v1 = acc[i][j][rr*2 + 1] + bias[col + 1];
                Ch[((size_t)row * N + col) >> 1] = f2h2(v0, v1);
                if (C)
                    *(float2*)(C + (size_t)row * N + col) = make_float2(v0, v1);
            }
        }
    }
}

// Wo GEMM with LN0 algebraically folded in.
// A = raw t0 (half). B = g0-scaled Wo (half).
// y = r*acc - r*mu*G[n] + B[n] + bo[n]; t1 = LN0(t0)[m,n] + relu(y).
__global__ __launch_bounds__(256, 2)
void gemm_wo(const unsigned short* __restrict__ A, const unsigned short* __restrict__ B,
             float* __restrict__ C, const float* __restrict__ T0,
             const float* __restrict__ Gw, const float* __restrict__ Bw,
             const float* __restrict__ g0, const float* __restrict__ b0,
             const float* __restrict__ bo, const float* __restrict__ Part)
{
    extern __shared__ __align__(16) unsigned short hsm[];
    __shared__ float sMu[128], sR[128];

    const int m0 = blockIdx.y * 128;
    const int n0 = blockIdx.x * 128;

    // finalize LN0 row stats for this CTA's 128 rows (from flash partials)
    if (threadIdx.x < 128) {
        const float2* pp = (const float2*)Part + (size_t)(m0 + threadIdx.x) * NH;
        float s = 0.f, sq = 0.f;
        #pragma unroll
        for (int i = 0; i < NH; i++) { float2 p = pp[i]; s += p.x; sq += p.y; }
        float mu = s * (1.f / DIM);
        float var = sq * (1.f / DIM) - mu * mu;
        sMu[threadIdx.x] = mu;
        sR[threadIdx.x]  = rsqrtf(var + LN_EPS);
    }

    GEMM_MAINLOOP(A, B, m0, n0)

    #pragma unroll
    for (int i = 0; i < 2; i++) {
        #pragma unroll
        for (int rr = 0; rr < 2; rr++) {
            const int local = mBase + i * 16 + g + rr * 8;
            const int row = m0 + local;
            const float mu  = sMu[local];
            const float r   = sR[local];
            const float rmu = r * mu;
            #pragma unroll
            for (int j = 0; j < 8; j++) {
                int col = n0 + nBase + j * 8 + 2 * q;
                float y0 = fmaf(r, acc[i][j][rr*2 + 0], -rmu * Gw[col    ]) + Bw[col    ] + bo[col    ];
                float y1 = fmaf(r, acc[i][j][rr*2 + 1], -rmu * Gw[col + 1]) + Bw[col + 1] + bo[col + 1];
                float2 t0v = *(const float2*)(T0 + (size_t)row * N + col);
                float R0 = (t0v.x - mu) * r * g0[col    ] + b0[col    ];
                float R1 = (t0v.y - mu) * r * g0[col + 1] + b0[col + 1];
                *(float2*)(C + (size_t)row * N + col) =
                    make_float2(R0 + fmaxf(y0, 0.f), R1 + fmaxf(y1, 0.f));
            }
        }
    }
}

// ---------------------------------------------------------------------------
// Fused flash attention (maxless softmax, MOFF). Epilogue additionally emits
// t0 as half and per-(row,head) {sum, sumsq} partials for the folded LN0.
// ---------------------------------------------------------------------------
#define FL_STH 72
#define FL_QB  (128*FL_STH*2)
#define FL_KB  (64*FL_STH*2)
#define FLASH_SMEM (FL_QB + 2*FL_KB + 2*FL_KB + 2*64*4)

__global__ __launch_bounds__(256, 2)
void flash_tc(const unsigned* __restrict__ Qh, const unsigned* __restrict__ Kh,
              const unsigned* __restrict__ Vh, const float* __restrict__ Qf,
              const float* __restrict__ pq, const float* __restrict__ pk,
              float* __restrict__ Om, unsigned* __restrict__ Omh,
              float* __restrict__ Part, float scale)
{
    extern __shared__ __align__(16) char fsm[];
    unsigned short* Qs = (unsigned short*)fsm;                     // [128][72]
    unsigned short* Ks = (unsigned short*)(fsm + FL_QB);           // [2][64][72]
    unsigned short* Vs = (unsigned short*)(fsm + FL_QB + 2*FL_KB); // [2][64][72]
    float* pks = (float*)(fsm + FL_QB + 4*FL_KB);                  // [2][64]

    const int bh = blockIdx.y;
    const int bz = bh >> 3, hz = bh & 7;
    const int m0 = blockIdx.x * 128;
    const int tid  = threadIdx.x;
    const int lane = tid & 31;
    const int w    = tid >> 5;
    const int g    = lane >> 2;
    const int q    = lane & 3;

    const size_t baseh = ((size_t)bz * SEQQ * DIM + hz * HD);
    const unsigned short* Qhp = (const unsigned short*)Qh + baseh;
    const unsigned short* Khp = (const unsigned short*)Kh + baseh;
    const unsigned short* Vhp = (const unsigned short*)Vh + baseh;
    const float* Qp = Qf + baseh;
    float*       Op = Om + baseh;
    unsigned short* Ohp = (unsigned short*)Omh + baseh;

    const int row0 = m0 + w * 16 + g;

    #pragma unroll
    for (int r = 0; r < 4; r++) {
        int f = tid + r * 256;
        int m = f >> 3, ch = (f & 7) * 8;
        uint4 t = *(const uint4*)(Qhp + (size_t)(m0 + m) * DIM + ch);
        *(uint4*)(Qs + m * FL_STH + ch) = t;
    }

    const unsigned qB = sm_addr(Qs + (w*16 + (lane & 7) + 8*((lane >> 3) & 1)) * FL_STH
                                  + (lane >> 4) * 8);
    const unsigned kB0 = sm_addr(Ks + ((lane & 7) + 8*(lane >> 4)) * FL_STH
                                   + ((lane >> 3) & 1) * 8);
    const unsigned vB0 = sm_addr(Vs + ((lane & 7) + 8*((lane >> 3) & 1)) * FL_STH
                                   + (lane >> 4) * 8);

    const float pq0  = pq[bz * SEQQ + row0];
    const float pq1  = pq[bz * SEQQ + row0 + 8];
    const float pq0s = pq0 * scale;
    const float pq1s = pq1 * scale;
    const float e0   = MOFF * pq0;
    const float e1   = MOFF * pq1;

    float o[8][4];
    #pragma unroll
    for (int j = 0; j < 8; j++)
        #pragma unroll
        for (int r = 0; r < 4; r++) o[j][r] = 0.f;

    float rl0 = 0.f, rl1 = 0.f;

    {
        #pragma unroll
        for (int r = 0; r < 2; r++) {
            int f = tid + r * 256;
            int n = f >> 3, ch = (f & 7) * 8;
            cp16(sm_addr(Ks + n * FL_STH + ch), Khp + (size_t)n * DIM + ch);
            cp16(sm_addr(Vs + n * FL_STH + ch), Vhp + (size_t)n * DIM + ch);
        }
        if (tid < 64) pks[tid] = pk[bz * SEQK + tid];
        cp_commit();
    }

    for (int t = 0; t < 16; t++) {
        const int buf = t & 1;

        if (t + 1 < 16) {
            const int n0n = (t + 1) * 64;
            const int bo_ = (buf ^ 1) * 64 * FL_STH;
            #pragma unroll
            for (int r = 0; r < 2; r++) {
                int f = tid + r * 256;
                int n = f >> 3, ch = (f & 7) * 8;
                cp16(sm_addr(Ks + bo_ + n * FL_STH + ch),
                     Khp + (size_t)(n0n + n) * DIM + ch);
                cp16(sm_addr(Vs + bo_ + n * FL_STH + ch),
                     Vhp + (size_t)(n0n + n) * DIM + ch);
            }
            if (tid < 64) pks[(buf ^ 1) * 64 + tid] = pk[bz * SEQK + n0n + tid];
            cp_commit();
            cp_wait<1>();
        } else {
            cp_wait<0>();
        }
        __syncthreads();

        const unsigned kB = kB0 + buf * FL_KB;
        const unsigned vB = vB0 + buf * FL_KB;
        const float* pkb = pks + buf * 64;

        float s[8][4];
        #pragma unroll
        for (int j = 0; j < 8; j++)
            #pragma unroll
            for (int r = 0; r < 4; r++) s[j][r] = 0.f;

        #pragma unroll
        for (int c = 0; c < 4; c++) {
            unsigned a[4];
            ldsm_x4(a[0], a[1], a[2], a[3], qB + 32*c);
            #pragma unroll
            for (int jp = 0; jp < 4; jp++) {
                unsigned b[4];
                ldsm_x4(b[0], b[1], b[2], b[3], kB + jp*2304 + 32*c);
                mma_f16(s[2*jp    ], a, b    );
                mma_f16(s[2*jp + 1], a, b + 2);
            }
        }

        #pragma unroll
        for (int j = 0; j < 8; j++) {
            const float pka = pkb[8*j + 2*q];
            const float pkv = pkb[8*j + 2*q + 1];
            float x0 = fmaf(pka, fmaf(pq0s, s[j][0], e0), -MOFF);
            float x1 = fmaf(pkv, fmaf(pq0s, s[j][1], e0), -MOFF);
            float x2 = fmaf(pka, fmaf(pq1s, s[j][2], e1), -MOFF);
            float x3 = fmaf(pkv, fmaf(pq1s, s[j][3], e1), -MOFF);
            x0 = __expf(x0); x1 = __expf(x1);
            x2 = __expf(x2); x3 = __expf(x3);
            rl0 += x0 + x1;
            rl1 += x2 + x3;
            s[j][0] = x0; s[j][1] = x1; s[j][2] = x2; s[j][3] = x3;
        }

        #pragma unroll
        for (int c = 0; c < 4; c++) {
            unsigned pf[4];
            pf[0] = f2h2(s[2*c    ][0], s[2*c    ][1]);
            pf[1] = f2h2(s[2*c    ][2], s[2*c    ][3]);
            pf[2] = f2h2(s[2*c + 1][0], s[2*c + 1][1]);
            pf[3] = f2h2(s[2*c + 1][2], s[2*c + 1][3]);
            #pragma unroll
            for (int jp = 0; jp < 4; jp++) {
                unsigned b[4];
                ldsm_x4t(b[0], b[1], b[2], b[3], vB + c*2304 + jp*32);
                mma_f16(o[2*jp    ], pf, b    );
                mma_f16(o[2*jp + 1], pf, b + 2);
            }
        }
        __syncthreads();
    }

    // --- row-sum reduction + epilogue (t0 f32 + t0 half + LN0 partials)
    rl0 += __shfl_xor_sync(0xffffffffu, rl0, 1);
    rl0 += __shfl_xor_sync(0xffffffffu, rl0, 2);
    rl1 += __shfl_xor_sync(0xffffffffu, rl1, 1);
    rl1 += __shfl_xor_sync(0xffffffffu, rl1, 2);
    const float il0 = 1.f / rl0;
    const float il1 = 1.f / rl1;

    float s0 = 0.f, ss0 = 0.f, s1 = 0.f, ss1 = 0.f;
    #pragma unroll
    for (int j = 0; j < 8; j++) {
        const int col = 8*j + 2*q;
        float2 r0 = *(const float2*)(Qp + (size_t)row0 * DIM + col);
        float2 r1 = *(const float2*)(Qp + (size_t)(row0 + 8) * DIM + col);
        float a0 = o[j][0] * il0 + r0.x;
        float a1 = o[j][1] * il0 + r0.y;
        float b0v = o[j][2] * il1 + r1.x;
        float b1v = o[j][3] * il1 + r1.y;
        *(float2*)(Op + (size_t)row0 * DIM + col) = make_float2(a0, a1);
        *(float2*)(Op + (size_t)(row0 + 8) * DIM + col) = make_float2(b0v, b1v);
        *(unsigned*)(Ohp + (size_t)row0 * DIM + col) = f2h2(a0, a1);
        *(unsigned*)(Ohp + (size_t)(row0 + 8) * DIM + col) = f2h2(b0v, b1v);
        s0 += a0 + a1;   ss0 += a0*a0 + a1*a1;
        s1 += b0v + b1v; ss1 += b0v*b0v + b1v*b1v;
    }
    s0  += __shfl_xor_sync(0xffffffffu, s0, 1);  s0  += __shfl_xor_sync(0xffffffffu, s0, 2);
    ss0 += __shfl_xor_sync(0xffffffffu, ss0, 1); ss0 += __shfl_xor_sync(0xffffffffu, ss0, 2);
    s1  += __shfl_xor_sync(0xffffffffu, s1, 1);  s1  += __shfl_xor_sync(0xffffffffu, s1, 2);
    ss1 += __shfl_xor_sync(0xffffffffu, ss1, 1); ss1 += __shfl_xor_sync(0xffffffffu, ss1, 2);
    if (q == 0) {
        const size_t gr0 = (size_t)bz * SEQQ + row0;
        *(float2*)(Part + (gr0 * NH + hz) * 2)       = make_float2(s0, ss0);
        *(float2*)(Part + ((gr0 + 8) * NH + hz) * 2) = make_float2(s1, ss1);
    }
}

// ---------------------------------------------------------------------------
// LayerNorm, 2 rows per 256-thread block.
// ---------------------------------------------------------------------------
__global__ __launch_bounds__(256)
void ln2_k(const float* __restrict__ X, float* __restrict__ Y,
           const float* __restrict__ gamma, const float* __restrict__ beta)
{
    const int tid = threadIdx.x;
    const int sec = tid >> 7;            // 0 or 1 (row within block)
    const int t   = tid & 127;
    const long row = (long)blockIdx.x * 2 + sec;
    const float* x = X + row * DIM;
    const int w = tid >> 5, l = tid & 31;
    __shared__ float sred[8];

    float4 v = *(const float4*)(x + t * 4);

    float s = v.x + v.y + v.z + v.w;
    #pragma unroll
    for (int o = 16; o > 0; o >>= 1) s += __shfl_xor_sync(0xffffffffu, s, o);
    if (l == 0) sred[w] = s;
    __syncthreads();
    float mu = (sred[sec*4+0] + sred[sec*4+1] + sred[sec*4+2] + sred[sec*4+3]) * (1.f/DIM);
    __syncthreads();

    v.x -= mu; v.y -= mu; v.z -= mu; v.w -= mu;
    float sq = v.x*v.x + v.y*v.y + v.z*v.z + v.w*v.w;
    #pragma unroll
    for (int o = 16; o > 0; o >>= 1) sq += __shfl_xor_sync(0xffffffffu, sq, o);
    if (l == 0) sred[w] = sq;
    __syncthreads();
    const float var = (sred[sec*4+0] + sred[sec*4+1] + sred[sec*4+2] + sred[sec*4+3]) * (1.f/DIM);
    const float r = rsqrtf(var + LN_EPS);

    const int c = t * 4;
    float4 gm = *(const float4*)(gamma + c);
    float4 bt = *(const float4*)(beta + c);
    *(float4*)(Y + row*DIM + c) = make_float4(
        v.x*r*gm.x + bt.x, v.y*r*gm.y + bt.y,
        v.z*r*gm.z + bt.z, v.w*r*gm.w + bt.w);
}

// ---------------------------------------------------------------------------
extern "C" void kernel_launch(void* const* d_in, const int* in_sizes, int n_in,
                              void* d_out, int out_size)
{
    (void)in_sizes; (void)n_in; (void)out_size;
    const float* queries = (const float*)d_in[0];
    const float* keys    = (const float*)d_in[1];
    const float* pq      = (const float*)d_in[2];
    const float* pk      = (const float*)d_in[3];
    // d_in[4] = num_heads (fixed 8)
    const float* Wq = (const float*)d_in[5];
    const float* bq = (const float*)d_in[6];
    const float* Wk = (const float*)d_in[7];
    const float* bk = (const float*)d_in[8];
    const float* Wv = (const float*)d_in[9];
    const float* bv = (const float*)d_in[10];
    const float* Wo = (const float*)d_in[11];
    const float* bo = (const float*)d_in[12];
    const float* g0 = (const float*)d_in[13];
    const float* b0 = (const float*)d_in[14];
    const float* g1 = (const float*)d_in[15];
    const float* b1 = (const float*)d_in[16];
    float* out = (float*)d_out;

    float *q, *t0, *t1, *part, *gw, *bw;
    unsigned *qh, *kh, *vh, *qin, *kin, *wq, *wk, *wv, *wo, *t0h;
    cudaGetSymbolAddress((void**)&q,    g_q);
    cudaGetSymbolAddress((void**)&qh,   g_qh);
    cudaGetSymbolAddress((void**)&kh,   g_kh);
    cudaGetSymbolAddress((void**)&vh,   g_vh);
    cudaGetSymbolAddress((void**)&qin,  g_qin);
    cudaGetSymbolAddress((void**)&kin,  g_kin);
    cudaGetSymbolAddress((void**)&wq,   g_wq);
    cudaGetSymbolAddress((void**)&wk,   g_wk);
    cudaGetSymbolAddress((void**)&wv,   g_wv);
    cudaGetSymbolAddress((void**)&wo,   g_wo);
    cudaGetSymbolAddress((void**)&t0,   g_t0);
    cudaGetSymbolAddress((void**)&t0h,  g_t0h);
    cudaGetSymbolAddress((void**)&t1,   g_t1);
    cudaGetSymbolAddress((void**)&part, g_part);
    cudaGetSymbolAddress((void**)&gw,   g_gw);
    cudaGetSymbolAddress((void**)&bw,   g_bw);

    const float att_scale = 1.0f / sqrtf((float)DIM);

    cudaFuncSetAttribute(gemm_qkv,
                         cudaFuncAttributeMaxDynamicSharedMemorySize, GEMM_SMEM);
    cudaFuncSetAttribute(gemm_wo,
                         cudaFuncAttributeMaxDynamicSharedMemorySize, GEMM_SMEM);
    cudaFuncSetAttribute(flash_tc,
                         cudaFuncAttributeMaxDynamicSharedMemorySize, FLASH_SMEM);

    // --- prep: conversions + Wo scaling + G/B colsums (one launch)
    {
        const int nBig = MROWS * DIM / 4;
        const int nW   = DIM * DIM / 4;
        dim3 gc((nBig + 255)/256, 7);
        prep_k<<<gc, 256>>>(queries, keys, Wq, Wk, Wv, Wo, g0, b0,
                            qin, kin, wq, wk, wv, wo, gw, bw, nBig, nW);
    }

    // --- q/k/v projections in one launch
    {
        dim3 grid(12, MROWS/128, 1);
        gemm_qkv<<<grid,256,GEMM_SMEM>>>(
            (const unsigned short*)qin, (const unsigned short*)kin,
            (const unsigned short*)wq, (const unsigned short*)wk,
            (const unsigned short*)wv,
            q, qh, kh, vh, bq, bk, bv);
    }

    // --- fused attention: t0 = qh + attn; also emits t0h + LN0 partials
    {
        dim3 grid(SEQQ/128, BATCH*NH);
        flash_tc<<<grid,256,FLASH_SMEM>>>(qh, kh, vh, q, pq, pk,
                                          t0, t0h, part, att_scale);
    }

    // --- t1 = LN0(t0) + relu(LN0(t0) @ Wo + bo)   [LN0 folded]
    {
        dim3 grid(DIM/128, MROWS/128, 1);
        gemm_wo<<<grid,256,GEMM_SMEM>>>(
            (const unsigned short*)t0h, (const unsigned short*)wo,
            t1, t0, gw, bw, g0, b0, bo, part);
    }

    // --- LN1 -> out
    ln2_k<<<MROWS/2, 256>>>(t1, out, g1, b1);
}

// round 17
// speedup vs baseline: 1.1391x; 1.1391x over previous
#include <cuda_runtime.h>
#include <math.h>

// Problem constants
#define BATCH 8
#define NH    8
#define SEQQ  1024
#define SEQK  1024
#define DIM   512
#define HD    64
#define MROWS (BATCH*SEQQ)   // 8192

#define LN_EPS   1e-5f
#define MOFF     9.0f        // mask offset: exp(-9)=1.23e-4, normal in fp16

static __device__ float    g_q  [BATCH*SEQQ*DIM];
static __device__ unsigned g_qh [BATCH*SEQQ*DIM/2];
static __device__ unsigned g_kh [BATCH*SEQK*DIM/2];
static __device__ unsigned g_vh [BATCH*SEQK*DIM/2];
static __device__ unsigned g_qin[BATCH*SEQQ*DIM/2];
static __device__ unsigned g_kin[BATCH*SEQK*DIM/2];
static __device__ unsigned g_wq [DIM*DIM/2];
static __device__ unsigned g_wk [DIM*DIM/2];
static __device__ unsigned g_wv [DIM*DIM/2];
static __device__ unsigned g_wo [DIM*DIM/2];
static __device__ float    g_t0 [BATCH*SEQQ*DIM];
static __device__ unsigned g_t0h[BATCH*SEQQ*DIM/2];
static __device__ float    g_t1 [BATCH*SEQQ*DIM];

#define EPI_BIAS       0
#define EPI_RELU_RESID 3

// ---------------------------------------------------------------------------
// helpers
// ---------------------------------------------------------------------------
__device__ __forceinline__ unsigned f2h2(float lo, float hi) {
    unsigned u;
    asm("{.reg .f16 l, h;\n\t"
        "cvt.rn.f16.f32 l, %1;\n\t"
        "cvt.rn.f16.f32 h, %2;\n\t"
        "mov.b32 %0, {l, h};}"
        : "=r"(u) : "f"(lo), "f"(hi));
    return u;
}

__device__ __forceinline__ void mma_f16(float* c, const unsigned* a, const unsigned* b) {
    asm volatile(
        "mma.sync.aligned.m16n8k16.row.col.f32.f16.f16.f32 "
        "{%0,%1,%2,%3},{%4,%5,%6,%7},{%8,%9},{%0,%1,%2,%3};"
        : "+f"(c[0]), "+f"(c[1]), "+f"(c[2]), "+f"(c[3])
        : "r"(a[0]), "r"(a[1]), "r"(a[2]), "r"(a[3]), "r"(b[0]), "r"(b[1]));
}

__device__ __forceinline__ void cp16(unsigned dst, const void* src) {
    asm volatile("cp.async.cg.shared.global [%0], [%1], 16;" :: "r"(dst), "l"(src));
}
__device__ __forceinline__ void cp_commit() {
    asm volatile("cp.async.commit_group;" ::: "memory");
}
template<int N>
__device__ __forceinline__ void cp_wait() {
    asm volatile("cp.async.wait_group %0;" :: "n"(N) : "memory");
}

__device__ __forceinline__ unsigned sm_addr(const void* p) {
    return (unsigned)__cvta_generic_to_shared(p);
}

__device__ __forceinline__ void ldsm_x4(unsigned& r0, unsigned& r1,
                                        unsigned& r2, unsigned& r3, unsigned a) {
    asm volatile("ldmatrix.sync.aligned.m8n8.x4.shared.b16 {%0,%1,%2,%3}, [%4];"
        : "=r"(r0), "=r"(r1), "=r"(r2), "=r"(r3) : "r"(a));
}
__device__ __forceinline__ void ldsm_x4t(unsigned& r0, unsigned& r1,
                                         unsigned& r2, unsigned& r3, unsigned a) {
    asm volatile("ldmatrix.sync.aligned.m8n8.x4.trans.shared.b16 {%0,%1,%2,%3}, [%4];"
        : "=r"(r0), "=r"(r1), "=r"(r2), "=r"(r3) : "r"(a));
}

// ---------------------------------------------------------------------------
// 6-way f32 -> half2 pack; blockIdx.y selects tensor (0,1 big; 2..5 weights)
// ---------------------------------------------------------------------------
__global__ __launch_bounds__(256)
void f2h6_k(const float* __restrict__ X0, const float* __restrict__ X1,
            const float* __restrict__ X2, const float* __restrict__ X3,
            const float* __restrict__ X4, const float* __restrict__ X5,
            unsigned* __restrict__ Y0, unsigned* __restrict__ Y1,
            unsigned* __restrict__ Y2, unsigned* __restrict__ Y3,
            unsigned* __restrict__ Y4, unsigned* __restrict__ Y5,
            int nBig, int nW)
{
    const float* X; unsigned* Y; int n4;
    switch (blockIdx.y) {
        case 0:  X = X0; Y = Y0; n4 = nBig; break;
        case 1:  X = X1; Y = Y1; n4 = nBig; break;
        case 2:  X = X2; Y = Y2; n4 = nW;   break;
        case 3:  X = X3; Y = Y3; n4 = nW;   break;
        case 4:  X = X4; Y = Y4; n4 = nW;   break;
        default: X = X5; Y = Y5; n4 = nW;   break;
    }
    int i = blockIdx.x * blockDim.x + threadIdx.x;
    if (i < n4) {
        float4 t = ((const float4*)X)[i];
        ((uint2*)Y)[i] = make_uint2(f2h2(t.x, t.y), f2h2(t.z, t.w));
    }
}

// ---------------------------------------------------------------------------
// Dense NN GEMM (half inputs): C = A @ B + epilogue. BM=BN=128, BK=32.
// ---------------------------------------------------------------------------
#define HA_ST 40
#define HB_ST 136
#define GEMM_SMEM ((4*128*HA_ST + 4*32*HB_ST) * 2)

template<int EPI>
__device__ __forceinline__
void gemm_body(const unsigned short* __restrict__ A,
               const unsigned short* __restrict__ B,
               float* __restrict__ C, unsigned* __restrict__ Ch,
               const float* __restrict__ bias, const float* __restrict__ R,
               int m0, int n0, unsigned short* hsm)
{
    unsigned short* As = hsm;                      // [4][128][40]
    unsigned short* Bs = hsm + 4*128*HA_ST;        // [4][32][136]

    const int K = DIM, N = DIM;
    const int tid  = threadIdx.x;
    const int lane = tid & 31;
    const int warp = tid >> 5;
    const int g    = lane >> 2;
    const int q    = lane & 3;
    const int mBase = (warp & 3) * 32;
    const int nBase = (warp >> 2) * 64;

    const int amr[2] = { tid >> 2,        (tid + 256) >> 2 };
    const int amc[2] = { (tid & 3) * 8,   ((tid + 256) & 3) * 8 };
    const int bkr[2] = { tid >> 4,        (tid + 256) >> 4 };
    const int bnc[2] = { (tid & 15) * 8,  ((tid + 256) & 15) * 8 };

    const unsigned aB0 = sm_addr(As) +
        ((mBase + (lane & 15)) * HA_ST + (lane >> 4) * 8) * 2;
    const unsigned bB0 = sm_addr(Bs) +
        (((lane & 7) + 8 * ((lane >> 3) & 1)) * HB_ST + nBase + (lane >> 4) * 8) * 2;

    float acc[2][8][4];
    #pragma unroll
    for (int i = 0; i < 2; i++)
        #pragma unroll
        for (int j = 0; j < 8; j++)
            #pragma unroll
            for (int r = 0; r < 4; r++) acc[i][j][r] = 0.f;

    const int NITER = K / 32;   // 16

    #pragma unroll
    for (int s = 0; s < 3; s++) {
        const int k0 = s * 32;
        #pragma unroll
        for (int r = 0; r < 2; r++) {
            cp16(sm_addr(As + (s*128 + amr[r])*HA_ST + amc[r]),
                 A + (size_t)(m0 + amr[r]) * K + k0 + amc[r]);
            cp16(sm_addr(Bs + (s*32 + bkr[r])*HB_ST + bnc[r]),
                 B + (size_t)(k0 + bkr[r]) * N + n0 + bnc[r]);
        }
        cp_commit();
    }

    for (int it = 0; it < NITER; it++) {
        cp_wait<2>();
        __syncthreads();

        if (it + 3 < NITER) {
            const int s  = (it + 3) & 3;
            const int k0 = (it + 3) * 32;
            #pragma unroll
            for (int r = 0; r < 2; r++) {
                cp16(sm_addr(As + (s*128 + amr[r])*HA_ST + amc[r]),
                     A + (size_t)(m0 + amr[r]) * K + k0 + amc[r]);
                cp16(sm_addr(Bs + (s*32 + bkr[r])*HB_ST + bnc[r]),
                     B + (size_t)(k0 + bkr[r]) * N + n0 + bnc[r]);
            }
        }
        cp_commit();

        const unsigned aB = aB0 + (it & 3) * 128 * HA_ST * 2;
        const unsigned bB = bB0 + (it & 3) * 32 * HB_ST * 2;

        #pragma unroll
        for (int kc = 0; kc < 2; kc++) {
            unsigned a0[4], a1[4];
            ldsm_x4(a0[0], a0[1], a0[2], a0[3], aB + kc*32);
            ldsm_x4(a1[0], a1[1], a1[2], a1[3], aB + 16*HA_ST*2 + kc*32);
            #pragma unroll
            for (int jp = 0; jp < 4; jp++) {
                unsigned b[4];
                ldsm_x4t(b[0], b[1], b[2], b[3], bB + kc*16*HB_ST*2 + jp*32);
                mma_f16(acc[0][2*jp    ], a0, b    );
                mma_f16(acc[0][2*jp + 1], a0, b + 2);
                mma_f16(acc[1][2*jp    ], a1, b    );
                mma_f16(acc[1][2*jp + 1], a1, b + 2);
            }
        }
        __syncthreads();
    }

    #pragma unroll
    for (int i = 0; i < 2; i++) {
        #pragma unroll
        for (int rr = 0; rr < 2; rr++) {
            int row = m0 + mBase + i * 16 + g + rr * 8;
            #pragma unroll
            for (int j = 0; j < 8; j++) {
                int col = n0 + nBase + j * 8 + 2 * q;
                float v0 = acc[i][j][rr*2 + 0];
                float v1 = acc[i][j][rr*2 + 1];
                if (EPI == EPI_BIAS) {
                    v0 += bias[col]; v1 += bias[col + 1];
                    Ch[((size_t)row * N + col) >> 1] = f2h2(v0, v1);
                    if (C)
                        *(float2*)(C + (size_t)row * N + col) = make_float2(v0, v1);
                } else { // EPI_RELU_RESID
                    v0 = R[(size_t)row*N + col    ] + fmaxf(v0 + bias[col    ], 0.f);
                    v1 = R[(size_t)row*N + col + 1] + fmaxf(v1 + bias[col + 1], 0.f);
                    *(float2*)(C + (size_t)row * N + col) = make_float2(v0, v1);
                }
            }
        }
    }
}

// All three projections in one launch: grid.x = 12; blockIdx.x>>2 selects.
__global__ __launch_bounds__(256, 2)
void gemm_qkv(const unsigned short* __restrict__ Aq, const unsigned short* __restrict__ Akv,
              const unsigned short* __restrict__ Bq, const unsigned short* __restrict__ Bk,
              const unsigned short* __restrict__ Bv,
              float* __restrict__ Cq, unsigned* __restrict__ Chq,
              unsigned* __restrict__ Chk, unsigned* __restrict__ Chv,
              const float* __restrict__ bq, const float* __restrict__ bk,
              const float* __restrict__ bv)
{
    extern __shared__ __align__(16) unsigned short hsm[];
    const int sel = blockIdx.x >> 2;
    const unsigned short* A = sel ? Akv : Aq;
    const unsigned short* B = (sel == 0) ? Bq : (sel == 1) ? Bk : Bv;
    unsigned* Ch            = (sel == 0) ? Chq : (sel == 1) ? Chk : Chv;
    const float* bias       = (sel == 0) ? bq : (sel == 1) ? bk : bv;
    float* C                = (sel == 0) ? Cq : (float*)0;
    gemm_body<EPI_BIAS>(A, B, C, Ch, bias, 0,
                        blockIdx.y * 128, (blockIdx.x & 3) * 128, hsm);
}

__global__ __launch_bounds__(256, 2)
void gemm_wo(const unsigned short* __restrict__ A, const unsigned short* __restrict__ B,
             float* __restrict__ C, const float* __restrict__ bias,
             const float* __restrict__ R)
{
    extern __shared__ __align__(16) unsigned short hsm[];
    gemm_body<EPI_RELU_RESID>(A, B, C, 0, bias, R,
                              blockIdx.y * 128, blockIdx.x * 128, hsm);
}

// ---------------------------------------------------------------------------
// Fused flash attention, maxless softmax with fp16-safe mask offset.
// ---------------------------------------------------------------------------
#define FL_STH 72
#define FL_QB  (128*FL_STH*2)            // 18432
#define FL_KB  (64*FL_STH*2)             // 9216
#define FLASH_SMEM (FL_QB + 2*FL_KB + 2*FL_KB + 2*64*4)

__global__ __launch_bounds__(256, 2)
void flash_tc(const unsigned* __restrict__ Qh, const unsigned* __restrict__ Kh,
              const unsigned* __restrict__ Vh, const float* __restrict__ Qf,
              const float* __restrict__ pq, const float* __restrict__ pk,
              float* __restrict__ Om, float scale)
{
    extern __shared__ __align__(16) char fsm[];
    unsigned short* Qs = (unsigned short*)fsm;                     // [128][72]
    unsigned short* Ks = (unsigned short*)(fsm + FL_QB);           // [2][64][72]
    unsigned short* Vs = (unsigned short*)(fsm + FL_QB + 2*FL_KB); // [2][64][72]
    float* pks = (float*)(fsm + FL_QB + 4*FL_KB);                  // [2][64]

    const int bh = blockIdx.y;
    const int bz = bh >> 3, hz = bh & 7;
    const int m0 = blockIdx.x * 128;
    const int tid  = threadIdx.x;
    const int lane = tid & 31;
    const int w    = tid >> 5;
    const int g    = lane >> 2;
    const int q    = lane & 3;

    const size_t baseh = ((size_t)bz * SEQQ * DIM + hz * HD);
    const unsigned short* Qhp = (const unsigned short*)Qh + baseh;
    const unsigned short* Khp = (const unsigned short*)Kh + baseh;
    const unsigned short* Vhp = (const unsigned short*)Vh + baseh;
    const float* Qp = Qf + baseh;
    float*       Op = Om + baseh;

    const int row0 = m0 + w * 16 + g;

    #pragma unroll
    for (int r = 0; r < 4; r++) {
        int f = tid + r * 256;
        int m = f >> 3, ch = (f & 7) * 8;
        uint4 t = *(const uint4*)(Qhp + (size_t)(m0 + m) * DIM + ch);
        *(uint4*)(Qs + m * FL_STH + ch) = t;
    }

    const unsigned qB = sm_addr(Qs + (w*16 + (lane & 7) + 8*((lane >> 3) & 1)) * FL_STH
                                  + (lane >> 4) * 8);
    const unsigned kB0 = sm_addr(Ks + ((lane & 7) + 8*(lane >> 4)) * FL_STH
                                   + ((lane >> 3) & 1) * 8);
    const unsigned vB0 = sm_addr(Vs + ((lane & 7) + 8*((lane >> 3) & 1)) * FL_STH
                                   + (lane >> 4) * 8);

    const float pq0  = pq[bz * SEQQ + row0];
    const float pq1  = pq[bz * SEQQ + row0 + 8];
    const float pq0s = pq0 * scale;
    const float pq1s = pq1 * scale;
    const float e0   = MOFF * pq0;
    const float e1   = MOFF * pq1;

    float o[8][4];
    #pragma unroll
    for (int j = 0; j < 8; j++)
        #pragma unroll
        for (int r = 0; r < 4; r++) o[j][r] = 0.f;

    float rl0 = 0.f, rl1 = 0.f;   // per-thread partial row sums

    {
        #pragma unroll
        for (int r = 0; r < 2; r++) {
            int f = tid + r * 256;
            int n = f >> 3, ch = (f & 7) * 8;
            cp16(sm_addr(Ks + n * FL_STH + ch), Khp + (size_t)n * DIM + ch);
            cp16(sm_addr(Vs + n * FL_STH + ch), Vhp + (size_t)n * DIM + ch);
        }
        if (tid < 64) pks[tid] = pk[bz * SEQK + tid];
        cp_commit();
    }

    for (int t = 0; t < 16; t++) {
        const int buf = t & 1;

        if (t + 1 < 16) {
            const int n0n = (t + 1) * 64;
            const int bo  = (buf ^ 1) * 64 * FL_STH;
            #pragma unroll
            for (int r = 0; r < 2; r++) {
                int f = tid + r * 256;
                int n = f >> 3, ch = (f & 7) * 8;
                cp16(sm_addr(Ks + bo + n * FL_STH + ch),
                     Khp + (size_t)(n0n + n) * DIM + ch);
                cp16(sm_addr(Vs + bo + n * FL_STH + ch),
                     Vhp + (size_t)(n0n + n) * DIM + ch);
            }
            if (tid < 64) pks[(buf ^ 1) * 64 + tid] = pk[bz * SEQK + n0n + tid];
            cp_commit();
            cp_wait<1>();
        } else {
            cp_wait<0>();
        }
        __syncthreads();

        const unsigned kB = kB0 + buf * FL_KB;
        const unsigned vB = vB0 + buf * FL_KB;
        const float* pkb = pks + buf * 64;

        float s[8][4];
        #pragma unroll
        for (int j = 0; j < 8; j++)
            #pragma unroll
            for (int r = 0; r < 4; r++) s[j][r] = 0.f;

        #pragma unroll
        for (int c = 0; c < 4; c++) {
            unsigned a[4];
            ldsm_x4(a[0], a[1], a[2], a[3], qB + 32*c);
            #pragma unroll
            for (int jp = 0; jp < 4; jp++) {
                unsigned b[4];
                ldsm_x4(b[0], b[1], b[2], b[3], kB + jp*2304 + 32*c);
                mma_f16(s[2*jp    ], a, b    );
                mma_f16(s[2*jp + 1], a, b + 2);
            }
        }

        // --- mask (2 fma/elem) + exp + partial row sums (no max machinery)
        #pragma unroll
        for (int j = 0; j < 8; j++) {
            const float pka = pkb[8*j + 2*q];
            const float pkv = pkb[8*j + 2*q + 1];
            float x0 = fmaf(pka, fmaf(pq0s, s[j][0], e0), -MOFF);
            float x1 = fmaf(pkv, fmaf(pq0s, s[j][1], e0), -MOFF);
            float x2 = fmaf(pka, fmaf(pq1s, s[j][2], e1), -MOFF);
            float x3 = fmaf(pkv, fmaf(pq1s, s[j][3], e1), -MOFF);
            x0 = __expf(x0); x1 = __expf(x1);
            x2 = __expf(x2); x3 = __expf(x3);
            rl0 += x0 + x1;
            rl1 += x2 + x3;
            s[j][0] = x0; s[j][1] = x1; s[j][2] = x2; s[j][3] = x3;
        }

        // --- O += P @ V
        #pragma unroll
        for (int c = 0; c < 4; c++) {
            unsigned pf[4];
            pf[0] = f2h2(s[2*c    ][0], s[2*c    ][1]);
            pf[1] = f2h2(s[2*c    ][2], s[2*c    ][3]);
            pf[2] = f2h2(s[2*c + 1][0], s[2*c + 1][1]);
            pf[3] = f2h2(s[2*c + 1][2], s[2*c + 1][3]);
            #pragma unroll
            for (int jp = 0; jp < 4; jp++) {
                unsigned b[4];
                ldsm_x4t(b[0], b[1], b[2], b[3], vB + c*2304 + jp*32);
                mma_f16(o[2*jp    ], pf, b    );
                mma_f16(o[2*jp + 1], pf, b + 2);
            }
        }
        __syncthreads();
    }

    // --- final row-sum reduction (once) + epilogue
    rl0 += __shfl_xor_sync(0xffffffffu, rl0, 1);
    rl0 += __shfl_xor_sync(0xffffffffu, rl0, 2);
    rl1 += __shfl_xor_sync(0xffffffffu, rl1, 1);
    rl1 += __shfl_xor_sync(0xffffffffu, rl1, 2);
    const float il0 = 1.f / rl0;
    const float il1 = 1.f / rl1;
    #pragma unroll
    for (int j = 0; j < 8; j++) {
        const int col = 8*j + 2*q;
        float2 r0 = *(const float2*)(Qp + (size_t)row0 * DIM + col);
        float2 r1 = *(const float2*)(Qp + (size_t)(row0 + 8) * DIM + col);
        *(float2*)(Op + (size_t)row0 * DIM + col) =
            make_float2(o[j][0] * il0 + r0.x, o[j][1] * il0 + r0.y);
        *(float2*)(Op + (size_t)(row0 + 8) * DIM + col) =
            make_float2(o[j][2] * il1 + r1.x, o[j][3] * il1 + r1.y);
    }
}

// ---------------------------------------------------------------------------
// LayerNorm over last dim (512), 2 rows per 256-thread block.
// Optional half2 output for the row handled.
// ---------------------------------------------------------------------------
__global__ __launch_bounds__(256)
void ln2_k(const float* __restrict__ X, float* __restrict__ Y,
           unsigned* __restrict__ Yh,
           const float* __restrict__ gamma, const float* __restrict__ beta)
{
    const int tid = threadIdx.x;
    const int sec = tid >> 7;            // row within block (0/1)
    const int t   = tid & 127;
    const long row = (long)blockIdx.x * 2 + sec;
    const float* x = X + row * DIM;
    const int w = tid >> 5, l = tid & 31;
    __shared__ float sred[8];

    float4 v = *(const float4*)(x + t * 4);

    float s = v.x + v.y + v.z + v.w;
    #pragma unroll
    for (int o = 16; o > 0; o >>= 1) s += __shfl_xor_sync(0xffffffffu, s, o);
    if (l == 0) sred[w] = s;
    __syncthreads();
    float mu = (sred[sec*4+0] + sred[sec*4+1] + sred[sec*4+2] + sred[sec*4+3]) * (1.f/DIM);
    __syncthreads();

    v.x -= mu; v.y -= mu; v.z -= mu; v.w -= mu;
    float sq = v.x*v.x + v.y*v.y + v.z*v.z + v.w*v.w;
    #pragma unroll
    for (int o = 16; o > 0; o >>= 1) sq += __shfl_xor_sync(0xffffffffu, sq, o);
    if (l == 0) sred[w] = sq;
    __syncthreads();
    const float var = (sred[sec*4+0] + sred[sec*4+1] + sred[sec*4+2] + sred[sec*4+3]) * (1.f/DIM);
    const float r = rsqrtf(var + LN_EPS);

    const int c = t * 4;
    float4 gm = *(const float4*)(gamma + c);
    float4 bt = *(const float4*)(beta + c);
    float y0 = v.x*r*gm.x + bt.x;
    float y1 = v.y*r*gm.y + bt.y;
    float y2 = v.z*r*gm.z + bt.z;
    float y3 = v.w*r*gm.w + bt.w;
    *(float4*)(Y + row*DIM + c) = make_float4(y0, y1, y2, y3);
    if (Yh)
        *(uint2*)(Yh + ((row*DIM + c) >> 1)) =
            make_uint2(f2h2(y0, y1), f2h2(y2, y3));
}

// ---------------------------------------------------------------------------
extern "C" void kernel_launch(void* const* d_in, const int* in_sizes, int n_in,
                              void* d_out, int out_size)
{
    (void)in_sizes; (void)n_in; (void)out_size;
    const float* queries = (const float*)d_in[0];
    const float* keys    = (const float*)d_in[1];
    const float* pq      = (const float*)d_in[2];
    const float* pk      = (const float*)d_in[3];
    // d_in[4] = num_heads (fixed 8)
    const float* Wq = (const float*)d_in[5];
    const float* bq = (const float*)d_in[6];
    const float* Wk = (const float*)d_in[7];
    const float* bk = (const float*)d_in[8];
    const float* Wv = (const float*)d_in[9];
    const float* bv = (const float*)d_in[10];
    const float* Wo = (const float*)d_in[11];
    const float* bo = (const float*)d_in[12];
    const float* g0 = (const float*)d_in[13];
    const float* b0 = (const float*)d_in[14];
    const float* g1 = (const float*)d_in[15];
    const float* b1 = (const float*)d_in[16];
    float* out = (float*)d_out;

    float *q, *t0, *t1;
    unsigned *qh, *kh, *vh, *qin, *kin, *wq, *wk, *wv, *wo, *t0h;
    cudaGetSymbolAddress((void**)&q,   g_q);
    cudaGetSymbolAddress((void**)&qh,  g_qh);
    cudaGetSymbolAddress((void**)&kh,  g_kh);
    cudaGetSymbolAddress((void**)&vh,  g_vh);
    cudaGetSymbolAddress((void**)&qin, g_qin);
    cudaGetSymbolAddress((void**)&kin, g_kin);
    cudaGetSymbolAddress((void**)&wq,  g_wq);
    cudaGetSymbolAddress((void**)&wk,  g_wk);
    cudaGetSymbolAddress((void**)&wv,  g_wv);
    cudaGetSymbolAddress((void**)&wo,  g_wo);
    cudaGetSymbolAddress((void**)&t0,  g_t0);
    cudaGetSymbolAddress((void**)&t0h, g_t0h);
    cudaGetSymbolAddress((void**)&t1,  g_t1);

    const float att_scale = 1.0f / sqrtf((float)DIM);

    cudaFuncSetAttribute(gemm_qkv,
                         cudaFuncAttributeMaxDynamicSharedMemorySize, GEMM_SMEM);
    cudaFuncSetAttribute(gemm_wo,
                         cudaFuncAttributeMaxDynamicSharedMemorySize, GEMM_SMEM);
    cudaFuncSetAttribute(flash_tc,
                         cudaFuncAttributeMaxDynamicSharedMemorySize, FLASH_SMEM);

    // --- pre-convert all 6 tensors in one launch
    {
        const int nBig = MROWS * DIM / 4;     // 1,048,576 float4 groups
        const int nW   = DIM * DIM / 4;       // 65,536
        dim3 gc((nBig + 255)/256, 6);
        f2h6_k<<<gc, 256>>>(queries, keys, Wq, Wk, Wv, Wo,
                            qin, kin, wq, wk, wv, wo, nBig, nW);
    }

    // --- q/k/v projections in one launch
    {
        dim3 grid(12, MROWS/128, 1);
        gemm_qkv<<<grid,256,GEMM_SMEM>>>(
            (const unsigned short*)qin, (const unsigned short*)kin,
            (const unsigned short*)wq, (const unsigned short*)wk,
            (const unsigned short*)wv,
            q, qh, kh, vh, bq, bk, bv);
    }

    // --- fused attention: t0 = qh + softmax(mask(QK^T)) V
    {
        dim3 grid(SEQQ/128, BATCH*NH);
        flash_tc<<<grid,256,FLASH_SMEM>>>(qh, kh, vh, q, pq, pk, t0, att_scale);
    }

    // --- LN0 (in place, + half copy for Wo GEMM)
    ln2_k<<<MROWS/2, 256>>>(t0, t0, t0h, g0, b0);

    // --- t1 = t0 + relu(t0 @ Wo + bo)
    {
        dim3 grid(DIM/128, MROWS/128, 1);
        gemm_wo<<<grid,256,GEMM_SMEM>>>(
            (const unsigned short*)t0h, (const unsigned short*)wo, t1, bo, t0);
    }

    // --- LN1 -> out
    ln2_k<<<MROWS/2, 256>>>(t1, out, 0, g1, b1);
}